// round 16
// baseline (speedup 1.0000x reference)
#include <cuda_runtime.h>
#include <cuda_bf16.h>
#include <math.h>
#include <stdint.h>

#define SEQ  4096
#define PSEQ 4608                                  // padded permuted row space (group offs 128-aligned)
#define CD   640
#define MATSZ ((size_t)SEQ * SEQ + (1u << 21))     // entity score arena

// ---- device scratch (static; no runtime allocation) ----
__device__ float g_xr[(size_t)SEQ * CD];           // tf32-rounded hidden_states
__device__ float g_wr[10ull * CD * CD];            // tf32-rounded weights (9 proj + Wo)
__device__ float g_proj[9ull * PSEQ * CD];         // 9 projections (tf32-rounded), PERMUTED rows
__device__ __nv_bfloat16 g_vbfT[2ull * CD * PSEQ]; // bf16 TRANSPOSED V (orig=0, outside=1): [col][row]
__device__ float g_scores[MATSZ];                  // entity score matrix (grouped)
__device__ float g_hs[(size_t)PSEQ * CD];          // attention output, permuted rows
__device__ float g_meanVo[CD];
__device__ float g_rowmask[PSEQ];                  // 1.0 for real rows, 0.0 for gaps
__device__ int   g_lab[SEQ];
__device__ int   g_outs[SEQ];
__device__ int   g_iperm[SEQ];                     // original row -> padded permuted row
__device__ int   d_off[4], d_cnt[4], d_cntOut[4], d_cntPad[4];
__device__ long long d_scbase[4];
__device__ int   d_qtileG[40], d_qtileQ0[40];
__device__ int   d_nqtiles;
__device__ int   d_rowg[PSEQ], d_rowloc[PSEQ];     // -1 for gap rows

// ---------------------------------------------------------------------------
__device__ __forceinline__ float tf32r(float x) {          // exact rna round to tf32
    uint32_t u; asm("cvt.rna.tf32.f32 %0, %1;" : "=r"(u) : "f"(x));
    return __uint_as_float(u);
}
__device__ __forceinline__ uint32_t rtf(float x) {          // bits + half-ulp (for fresh fp32 operands)
    return __float_as_uint(x) + 0x1000u;
}
__device__ __forceinline__ void mma_tf32(float d[4], const uint32_t a[4], const uint32_t b[2]) {
    asm volatile(
        "mma.sync.aligned.m16n8k8.row.col.f32.tf32.tf32.f32 "
        "{%0,%1,%2,%3}, {%4,%5,%6,%7}, {%8,%9}, {%0,%1,%2,%3};\n"
        : "+f"(d[0]), "+f"(d[1]), "+f"(d[2]), "+f"(d[3])
        : "r"(a[0]), "r"(a[1]), "r"(a[2]), "r"(a[3]), "r"(b[0]), "r"(b[1]));
}
__device__ __forceinline__ void mma_bf16(float d[4], const uint32_t a[4], const uint32_t b[2]) {
    asm volatile(
        "mma.sync.aligned.m16n8k16.row.col.f32.bf16.bf16.f32 "
        "{%0,%1,%2,%3}, {%4,%5,%6,%7}, {%8,%9}, {%0,%1,%2,%3};\n"
        : "+f"(d[0]), "+f"(d[1]), "+f"(d[2]), "+f"(d[3])
        : "r"(a[0]), "r"(a[1]), "r"(a[2]), "r"(a[3]), "r"(b[0]), "r"(b[1]));
}
__device__ __forceinline__ uint32_t bfpack(float lo, float hi) {   // lo -> bits[15:0]
    uint32_t d; asm("cvt.rn.bf16x2.f32 %0, %1, %2;" : "=r"(d) : "f"(hi), "f"(lo)); return d;
}
__device__ __forceinline__ uint32_t smem_u32(const void* p) {
    return (uint32_t)__cvta_generic_to_shared(p);
}
__device__ __forceinline__ void cp16(uint32_t dst, const void* src, int nbytes) {
    asm volatile("cp.async.cg.shared.global [%0], [%1], 16, %2;\n"
                 :: "r"(dst), "l"(src), "r"(nbytes));
}
#define CP_COMMIT() asm volatile("cp.async.commit_group;\n")
#define CP_WAIT1()  asm volatile("cp.async.wait_group 1;\n")

// ---------------------------------------------------------------------------
struct W10 { const float* w[10]; };

__global__ void round_x_kernel(const float* __restrict__ X) {
    size_t i = (size_t)blockIdx.x * blockDim.x + threadIdx.x;
    if (i < (size_t)SEQ * CD) g_xr[i] = tf32r(X[i]);
}
__global__ void round_w_kernel(W10 ws) {
    int z = blockIdx.y;
    size_t i = (size_t)blockIdx.x * blockDim.x + threadIdx.x;
    if (i < (size_t)CD * CD) g_wr[(size_t)z * CD * CD + i] = tf32r(ws.w[z][i]);
}

// ---------------------------------------------------------------------------
__global__ void labels_kernel(const int* __restrict__ mask,
                              const int* __restrict__ inp) {
    int t = blockIdx.x * blockDim.x + threadIdx.x;
    if (t < CD) g_meanVo[t] = 0.f;
    if (t >= SEQ) return;
    int i = t >> 6, j = t & 63;
    int idx = (i * 8) * 512 + j * 8;
    g_lab[t]  = mask[idx];
    g_outs[t] = (inp[idx] == 0) ? 1 : 0;
}

__global__ void zero_hs_kernel() {
    size_t i = (size_t)blockIdx.x * blockDim.x + threadIdx.x;
    if (i < (size_t)PSEQ * CD / 4)
        ((float4*)g_hs)[i] = make_float4(0.f, 0.f, 0.f, 0.f);
}

// ---------------------------------------------------------------------------
// prep: bucket sort by (label, !outside); group offsets 128-ALIGNED (padded)
// ---------------------------------------------------------------------------
__global__ void prep_kernel() {
    __shared__ int cnt8[8], off8[8], cur8[8];
    int tid = threadIdx.x;
    if (tid < 8) cnt8[tid] = 0;
    __syncthreads();
    for (int t = tid; t < SEQ; t += 256) {
        int b = g_lab[t] * 2 + (g_outs[t] ? 0 : 1);
        atomicAdd(&cnt8[b], 1);
    }
    __syncthreads();
    if (tid == 0) {
        long long sb = 0; int nq = 0; int cum = 0;
        for (int g = 0; g < 4; g++) {
            int c = cnt8[2 * g] + cnt8[2 * g + 1];
            d_off[g] = cum;
            off8[2 * g] = cum; off8[2 * g + 1] = cum + cnt8[2 * g];
            d_cnt[g] = c; d_cntOut[g] = cnt8[2 * g];
            int pad = ((c + 127) >> 7) << 7;
            d_cntPad[g] = pad;
            d_scbase[g] = sb; sb += (long long)pad * pad;
            for (int j = 0; j < c; j += 128) { d_qtileG[nq] = g; d_qtileQ0[nq] = j; nq++; }
            cum = (cum + c + 127) & ~127;
        }
        d_nqtiles = nq;
    }
    __syncthreads();
    if (tid < 8) cur8[tid] = off8[tid];
    __syncthreads();
    for (int t = tid; t < SEQ; t += 256) {
        int b = g_lab[t] * 2 + (g_outs[t] ? 0 : 1);
        g_iperm[t] = atomicAdd(&cur8[b], 1);
    }
    __syncthreads();
    for (int i = tid; i < PSEQ; i += 256) {
        int gg = -1, loc = 0;
        for (int g = 0; g < 4; g++)
            if (i >= d_off[g] && i < d_off[g] + d_cnt[g]) { gg = g; loc = i - d_off[g]; }
        d_rowg[i] = gg; d_rowloc[i] = loc;
        g_rowmask[i] = (gg >= 0) ? 1.0f : 0.0f;
    }
}

// ---------------------------------------------------------------------------
// 9 projections via tf32 mma + cp.async over PRE-ROUNDED X/W (no per-fragment
// rounding). Outputs stored tf32-rounded; V (z=2,8) also emitted bf16-T.
// ---------------------------------------------------------------------------
__global__ __launch_bounds__(256) void proj_kernel() {
    __shared__ float Xs[2][128 * 20];
    __shared__ float Bs[2][128 * 20];
    __shared__ int ip[128];
    int z = blockIdx.z;
    const float* X = g_xr;
    const float* W = g_wr + (size_t)z * CD * CD;
    float* Y = g_proj + (size_t)z * PSEQ * CD;
    int n0 = blockIdx.x * 128, m0 = blockIdx.y * 128;
    int tid = threadIdx.x, lane = tid & 31, warp = tid >> 5;
    int wm = warp & 3, wn = warp >> 2;
    if (tid < 128) ip[tid] = g_iperm[m0 + tid];
    uint32_t xb = smem_u32(Xs), bb = smem_u32(Bs);

    for (int ch = tid; ch < 512; ch += 256) {
        int r = ch >> 2, c4 = (ch & 3) * 4;
        cp16(xb + (r * 20 + c4) * 4, X + (size_t)(m0 + r) * CD + c4, 16);
        cp16(bb + (r * 20 + c4) * 4, W + (size_t)(n0 + r) * CD + c4, 16);
    }
    CP_COMMIT();

    float acc[2][8][4] = {};
    for (int s = 0; s < 40; s++) {
        if (s + 1 < 40) {
            int k0 = (s + 1) * 16;
            int bo = ((s + 1) & 1) * 2560;
            for (int ch = tid; ch < 512; ch += 256) {
                int r = ch >> 2, c4 = (ch & 3) * 4;
                cp16(xb + (bo + r * 20 + c4) * 4, X + (size_t)(m0 + r) * CD + k0 + c4, 16);
                cp16(bb + (bo + r * 20 + c4) * 4, W + (size_t)(n0 + r) * CD + k0 + c4, 16);
            }
        }
        CP_COMMIT(); CP_WAIT1();
        __syncthreads();
        const uint32_t* Xb = (const uint32_t*)Xs[s & 1];
        const uint32_t* Bb = (const uint32_t*)Bs[s & 1];
        #pragma unroll
        for (int k8 = 0; k8 < 16; k8 += 8) {
            int ac = k8 + (lane & 3);
            int ar = wm * 32 + (lane >> 2);
            uint32_t a[2][4];
            #pragma unroll
            for (int i = 0; i < 2; i++) {
                a[i][0] = Xb[(ar + i * 16) * 20 + ac];
                a[i][1] = Xb[(ar + i * 16 + 8) * 20 + ac];
                a[i][2] = Xb[(ar + i * 16) * 20 + ac + 4];
                a[i][3] = Xb[(ar + i * 16 + 8) * 20 + ac + 4];
            }
            #pragma unroll
            for (int j = 0; j < 8; j++) {
                int bc = wn * 64 + j * 8 + (lane >> 2);
                uint32_t b[2] = { Bb[bc * 20 + ac], Bb[bc * 20 + ac + 4] };
                mma_tf32(acc[0][j], a[0], b);
                mma_tf32(acc[1][j], a[1], b);
            }
        }
        __syncthreads();
    }
    int mi = wm * 32 + (lane >> 2);
    int nc = n0 + wn * 64 + 2 * (lane & 3);
    #pragma unroll
    for (int i = 0; i < 2; i++) {
        int pr0 = ip[mi + i * 16], pr1 = ip[mi + i * 16 + 8];
        #pragma unroll
        for (int j = 0; j < 8; j++) {
            int c = nc + j * 8;
            *(float2*)&Y[(size_t)pr0 * CD + c] =
                make_float2(tf32r(acc[i][j][0]), tf32r(acc[i][j][1]));
            *(float2*)&Y[(size_t)pr1 * CD + c] =
                make_float2(tf32r(acc[i][j][2]), tf32r(acc[i][j][3]));
        }
    }
    if (z == 2 || z == 8) {
        __nv_bfloat16* VT = g_vbfT + (z == 8 ? (size_t)CD * PSEQ : 0);
        #pragma unroll
        for (int i = 0; i < 2; i++) {
            int pr0 = ip[mi + i * 16], pr1 = ip[mi + i * 16 + 8];
            #pragma unroll
            for (int j = 0; j < 8; j++) {
                int c = nc + j * 8;
                VT[(size_t)c * PSEQ + pr0]       = __float2bfloat16(acc[i][j][0]);
                VT[(size_t)(c + 1) * PSEQ + pr0] = __float2bfloat16(acc[i][j][1]);
                VT[(size_t)c * PSEQ + pr1]       = __float2bfloat16(acc[i][j][2]);
                VT[(size_t)(c + 1) * PSEQ + pr1] = __float2bfloat16(acc[i][j][3]);
            }
        }
    }
}

// ---------------------------------------------------------------------------
// FLASH attention, BOTH d=80 branches: grid (qtile<=40, head, branch)
// Q/K pre-rounded tf32 (no per-fragment rounding). Epilogue atomicAdd.
// K-tile = 64 keys. SMEM 109,056 B -> 2 CTAs/SM.
// ---------------------------------------------------------------------------
#define QK_STRIDE 84
#define Q_FLOATS  (128 * QK_STRIDE)               // 10752
#define K_FLOATS  (64 * QK_STRIDE)                // 5376 per buffer
#define V_WORDS   (80 * 36)                       // 2880 per buffer
#define FA_SMEM_BYTES ((Q_FLOATS + 2 * K_FLOATS + 2 * V_WORDS) * 4)   // 109056

__global__ __launch_bounds__(256, 2) void fa_kernel(float scale) {
    extern __shared__ float sm[];
    float* Qs = sm;                                   // 128 x 84
    float* Ks = sm + Q_FLOATS;                        // 2 x 64 x 84
    uint32_t* VT = (uint32_t*)(sm + Q_FLOATS + 2 * K_FLOATS);  // 2 x 80 x 36 words

    int qt = blockIdx.x;
    if (qt >= d_nqtiles) return;
    int branch = blockIdx.z;
    int qsel = branch ? 6 : 0;
    int ksel = branch ? 7 : 1;
    int g = d_qtileG[qt], q0 = d_qtileQ0[qt];
    int cnt = d_cnt[g];
    int len = branch ? d_cntOut[g] : cnt;
    if (len == 0) return;
    int off = d_off[g];
    int z = blockIdx.y;
    const float* Q = g_proj + (size_t)qsel * PSEQ * CD;
    const float* K = g_proj + (size_t)ksel * PSEQ * CD;
    const __nv_bfloat16* Vsrc = g_vbfT + (size_t)branch * CD * PSEQ;

    int tid = threadIdx.x, lane = tid & 31, w = tid >> 5;
    int t2 = (lane & 3) * 2;
    int rbase = w * 16 + (lane >> 2);
    uint32_t qa = smem_u32(Qs), ka = smem_u32(Ks), va = smem_u32(VT);

    for (int ch = tid; ch < 2560; ch += 256) {
        int r = ch / 20, c4 = (ch % 20) * 4;
        int qr = q0 + r; int nb = (qr < cnt) ? 16 : 0; if (qr >= cnt) qr = cnt - 1;
        cp16(qa + (r * QK_STRIDE + c4) * 4, Q + (size_t)(off + qr) * CD + z * 80 + c4, nb);
    }
    for (int ch = tid; ch < 1280; ch += 256) {
        int r = ch / 20, c4 = (ch % 20) * 4;
        int kr = r; int nb = (kr < len) ? 16 : 0; if (kr >= len) kr = len - 1;
        cp16(ka + (r * QK_STRIDE + c4) * 4, K + (size_t)(off + kr) * CD + z * 80 + c4, nb);
    }
    for (int ch = tid; ch < 640; ch += 256) {
        int n = ch >> 3, r8 = ch & 7;
        int row = r8 * 8;
        int nb = (len - row) * 2; nb = nb < 0 ? 0 : (nb > 16 ? 16 : nb);
        int rowc = (row < len) ? row : 0;
        cp16(va + (n * 36 + r8 * 4) * 4,
             Vsrc + (size_t)(z * 80 + n) * PSEQ + off + rowc, nb);
    }
    CP_COMMIT();

    float accO[10][4] = {};
    float m_run[2] = {-1e30f, -1e30f}, l_run[2] = {0.f, 0.f};
    int nkt = (len + 63) >> 6;

    for (int it = 0; it < nkt; it++) {
        int kt = it * 64;
        if (it + 1 < nkt) {
            int ktn = kt + 64;
            int bo = (it + 1) & 1;
            for (int ch = tid; ch < 1280; ch += 256) {
                int r = ch / 20, c4 = (ch % 20) * 4;
                int kr = ktn + r; int nb = (kr < len) ? 16 : 0; if (kr >= len) kr = len - 1;
                cp16(ka + (bo * K_FLOATS + r * QK_STRIDE + c4) * 4,
                     K + (size_t)(off + kr) * CD + z * 80 + c4, nb);
            }
            for (int ch = tid; ch < 640; ch += 256) {
                int n = ch >> 3, r8 = ch & 7;
                int row = ktn + r8 * 8;
                int nb = (len - row) * 2; nb = nb < 0 ? 0 : (nb > 16 ? 16 : nb);
                int rowc = (row < len) ? row : 0;
                cp16(va + (bo * V_WORDS + n * 36 + r8 * 4) * 4,
                     Vsrc + (size_t)(z * 80 + n) * PSEQ + off + rowc, nb);
            }
        }
        CP_COMMIT(); CP_WAIT1();
        __syncthreads();
        const uint32_t* Kb = (const uint32_t*)(Ks + (it & 1) * K_FLOATS);
        const uint32_t* Qw = (const uint32_t*)Qs;
        const uint32_t* Vb = VT + (it & 1) * V_WORDS;

        float accS[8][4];
        #pragma unroll
        for (int jj = 0; jj < 8; jj++)
            accS[jj][0] = accS[jj][1] = accS[jj][2] = accS[jj][3] = 0.f;
        #pragma unroll
        for (int s8 = 0; s8 < 80; s8 += 8) {
            int ac = s8 + (lane & 3);
            uint32_t a[4];
            a[0] = Qw[rbase * QK_STRIDE + ac];
            a[1] = Qw[(rbase + 8) * QK_STRIDE + ac];
            a[2] = Qw[rbase * QK_STRIDE + ac + 4];
            a[3] = Qw[(rbase + 8) * QK_STRIDE + ac + 4];
            #pragma unroll
            for (int jj = 0; jj < 8; jj++) {
                int bc = jj * 8 + (lane >> 2);
                uint32_t b[2] = { Kb[bc * QK_STRIDE + ac], Kb[bc * QK_STRIDE + ac + 4] };
                mma_tf32(accS[jj], a, b);
            }
        }
        if (kt + 64 > len) {
            #pragma unroll
            for (int jj = 0; jj < 8; jj++) {
                int c0 = kt + jj * 8 + t2;
                if (c0 >= len)     { accS[jj][0] = -1e30f; accS[jj][2] = -1e30f; }
                if (c0 + 1 >= len) { accS[jj][1] = -1e30f; accS[jj][3] = -1e30f; }
            }
        }
        float mt0 = -1e30f, mt1 = -1e30f;
        #pragma unroll
        for (int jj = 0; jj < 8; jj++) {
            #pragma unroll
            for (int e = 0; e < 4; e++) accS[jj][e] *= scale;
            mt0 = fmaxf(mt0, fmaxf(accS[jj][0], accS[jj][1]));
            mt1 = fmaxf(mt1, fmaxf(accS[jj][2], accS[jj][3]));
        }
        mt0 = fmaxf(mt0, __shfl_xor_sync(0xffffffffu, mt0, 1));
        mt0 = fmaxf(mt0, __shfl_xor_sync(0xffffffffu, mt0, 2));
        mt1 = fmaxf(mt1, __shfl_xor_sync(0xffffffffu, mt1, 1));
        mt1 = fmaxf(mt1, __shfl_xor_sync(0xffffffffu, mt1, 2));
        float mn0 = fmaxf(m_run[0], mt0), mn1 = fmaxf(m_run[1], mt1);
        float f0 = __expf(m_run[0] - mn0), f1 = __expf(m_run[1] - mn1);
        m_run[0] = mn0; m_run[1] = mn1;
        float s0 = 0.f, s1 = 0.f;
        #pragma unroll
        for (int jj = 0; jj < 8; jj++) {
            accS[jj][0] = __expf(accS[jj][0] - mn0); s0 += accS[jj][0];
            accS[jj][1] = __expf(accS[jj][1] - mn0); s0 += accS[jj][1];
            accS[jj][2] = __expf(accS[jj][2] - mn1); s1 += accS[jj][2];
            accS[jj][3] = __expf(accS[jj][3] - mn1); s1 += accS[jj][3];
        }
        s0 += __shfl_xor_sync(0xffffffffu, s0, 1);
        s0 += __shfl_xor_sync(0xffffffffu, s0, 2);
        s1 += __shfl_xor_sync(0xffffffffu, s1, 1);
        s1 += __shfl_xor_sync(0xffffffffu, s1, 2);
        l_run[0] = l_run[0] * f0 + s0;
        l_run[1] = l_run[1] * f1 + s1;
        #pragma unroll
        for (int c = 0; c < 10; c++) {
            accO[c][0] *= f0; accO[c][1] *= f0; accO[c][2] *= f1; accO[c][3] *= f1;
        }
        #pragma unroll
        for (int u = 0; u < 4; u++) {
            uint32_t pa[4];
            pa[0] = bfpack(accS[2 * u][0],     accS[2 * u][1]);
            pa[1] = bfpack(accS[2 * u][2],     accS[2 * u][3]);
            pa[2] = bfpack(accS[2 * u + 1][0], accS[2 * u + 1][1]);
            pa[3] = bfpack(accS[2 * u + 1][2], accS[2 * u + 1][3]);
            #pragma unroll
            for (int c = 0; c < 10; c++) {
                int base = (c * 8 + (lane >> 2)) * 36 + u * 8 + (lane & 3);
                uint32_t b[2] = { Vb[base], Vb[base + 4] };
                mma_bf16(accO[c], pa, b);
            }
        }
        __syncthreads();
    }

    float inv0 = 1.0f / l_run[0], inv1 = 1.0f / l_run[1];
    int r0 = q0 + w * 16 + (lane >> 2);
    int r1 = r0 + 8;
    int cb = z * 80 + t2;
    #pragma unroll
    for (int c = 0; c < 10; c++) {
        int col = cb + c * 8;
        if (r0 < cnt) {
            size_t o = (size_t)(off + r0) * CD + col;
            atomicAdd(&g_hs[o],     accO[c][0] * inv0);
            atomicAdd(&g_hs[o + 1], accO[c][1] * inv0);
        }
        if (r1 < cnt) {
            size_t o = (size_t)(off + r1) * CD + col;
            atomicAdd(&g_hs[o],     accO[c][2] * inv1);
            atomicAdd(&g_hs[o + 1], accO[c][3] * inv1);
        }
    }
}

// ---------------------------------------------------------------------------
// ENTITY branch (d=640): scores (tf32, pre-rounded Q/K) -> softmax -> AV
// ---------------------------------------------------------------------------
__global__ __launch_bounds__(256) void scores_kernel(int qsel, int ksel,
                                                     int headDim, float scale) {
    __shared__ float Qs[2][128 * 20];
    __shared__ float Ks[2][128 * 20];
    int qt = blockIdx.x;
    if (qt >= d_nqtiles) return;
    int g = d_qtileG[qt], q0 = d_qtileQ0[qt];
    int cnt = d_cnt[g];
    int len = cnt;
    int k0t = blockIdx.y * 128;
    if (k0t >= len) return;
    int off = d_off[g];
    int stride = d_cntPad[g];
    const float* Q = g_proj + (size_t)qsel * PSEQ * CD;
    const float* K = g_proj + (size_t)ksel * PSEQ * CD;
    float* Sc = g_scores + (size_t)d_scbase[g];
    int tid = threadIdx.x, lane = tid & 31, warp = tid >> 5;
    int wm = warp & 3, wn = warp >> 2;
    uint32_t qb = smem_u32(Qs), kb = smem_u32(Ks);
    int NS = headDim / 16;

    for (int ch = tid; ch < 512; ch += 256) {
        int r = ch >> 2, c4 = (ch & 3) * 4;
        int qr = q0 + r, kr = k0t + r;
        int qv = (qr < cnt) ? 16 : 0;
        int kv = (kr < len) ? 16 : 0;
        if (qr >= cnt) qr = cnt - 1;
        if (kr >= len) kr = len - 1;
        cp16(qb + (r * 20 + c4) * 4, Q + (size_t)(off + qr) * CD + c4, qv);
        cp16(kb + (r * 20 + c4) * 4, K + (size_t)(off + kr) * CD + c4, kv);
    }
    CP_COMMIT();

    float acc[2][8][4] = {};
    for (int s = 0; s < NS; s++) {
        if (s + 1 < NS) {
            int k0 = (s + 1) * 16;
            int bo = ((s + 1) & 1) * 2560;
            for (int ch = tid; ch < 512; ch += 256) {
                int r = ch >> 2, c4 = (ch & 3) * 4;
                int qr = q0 + r, kr = k0t + r;
                int qv = (qr < cnt) ? 16 : 0;
                int kv = (kr < len) ? 16 : 0;
                if (qr >= cnt) qr = cnt - 1;
                if (kr >= len) kr = len - 1;
                cp16(qb + (bo + r * 20 + c4) * 4, Q + (size_t)(off + qr) * CD + k0 + c4, qv);
                cp16(kb + (bo + r * 20 + c4) * 4, K + (size_t)(off + kr) * CD + k0 + c4, kv);
            }
        }
        CP_COMMIT(); CP_WAIT1();
        __syncthreads();
        const uint32_t* Qb = (const uint32_t*)Qs[s & 1];
        const uint32_t* Kb = (const uint32_t*)Ks[s & 1];
        #pragma unroll
        for (int k8 = 0; k8 < 16; k8 += 8) {
            int ac = k8 + (lane & 3);
            int ar = wm * 32 + (lane >> 2);
            uint32_t a[2][4];
            #pragma unroll
            for (int i = 0; i < 2; i++) {
                a[i][0] = Qb[(ar + i * 16) * 20 + ac];
                a[i][1] = Qb[(ar + i * 16 + 8) * 20 + ac];
                a[i][2] = Qb[(ar + i * 16) * 20 + ac + 4];
                a[i][3] = Qb[(ar + i * 16 + 8) * 20 + ac + 4];
            }
            #pragma unroll
            for (int j = 0; j < 8; j++) {
                int bc = wn * 64 + j * 8 + (lane >> 2);
                uint32_t b[2] = { Kb[bc * 20 + ac], Kb[bc * 20 + ac + 4] };
                mma_tf32(acc[0][j], a[0], b);
                mma_tf32(acc[1][j], a[1], b);
            }
        }
        __syncthreads();
    }
    int mr = q0 + wm * 32 + (lane >> 2);
    int nc = k0t + wn * 64 + 2 * (lane & 3);
    #pragma unroll
    for (int i = 0; i < 2; i++) {
        int r0 = mr + i * 16;
        #pragma unroll
        for (int j = 0; j < 8; j++) {
            int c = nc + j * 8;
            *(float2*)&Sc[(size_t)r0 * stride + c] =
                make_float2(acc[i][j][0] * scale, acc[i][j][1] * scale);
            *(float2*)&Sc[(size_t)(r0 + 8) * stride + c] =
                make_float2(acc[i][j][2] * scale, acc[i][j][3] * scale);
        }
    }
}

__global__ __launch_bounds__(256) void softmax_kernel() {
    __shared__ float buf[SEQ];
    __shared__ float red[256];
    int row = blockIdx.x;
    int g = d_rowg[row];
    if (g < 0) return;
    int rl = d_rowloc[row];
    int len = d_cnt[g];
    float* p = g_scores + (size_t)d_scbase[g] + (size_t)rl * d_cntPad[g];
    int tid = threadIdx.x;
    float mx = -INFINITY;
    for (int i = tid; i < len; i += 256) { float v = p[i]; buf[i] = v; mx = fmaxf(mx, v); }
    red[tid] = mx; __syncthreads();
    for (int s = 128; s > 0; s >>= 1) {
        if (tid < s) red[tid] = fmaxf(red[tid], red[tid + s]);
        __syncthreads();
    }
    mx = red[0]; __syncthreads();
    float sum = 0.f;
    for (int i = tid; i < len; i += 256) { float e = __expf(buf[i] - mx); buf[i] = e; sum += e; }
    red[tid] = sum; __syncthreads();
    for (int s = 128; s > 0; s >>= 1) {
        if (tid < s) red[tid] += red[tid + s];
        __syncthreads();
    }
    float inv = 1.0f / red[0];
    for (int i = tid; i < len; i += 256) p[i] = buf[i] * inv;
}

__global__ __launch_bounds__(256) void av_kernel(int vsel) {
    __shared__ float Ps[2][128 * 20];
    __shared__ float Vs[2][16 * 88];
    int qt = blockIdx.x;
    if (qt >= d_nqtiles) return;
    int g = d_qtileG[qt], q0 = d_qtileQ0[qt];
    int cnt = d_cnt[g];
    int len = cnt;
    int off = d_off[g];
    int stride = d_cntPad[g];
    int c0 = blockIdx.y * 80;
    const float* P = g_scores + (size_t)d_scbase[g];
    const float* V = g_proj + (size_t)vsel * PSEQ * CD;
    int tid = threadIdx.x, lane = tid & 31, warp = tid >> 5;
    int wm = warp & 3, wn = warp >> 2;
    uint32_t pb = smem_u32(Ps), vb = smem_u32(Vs);
    int NS = (len + 15) >> 4;

    for (int ch = tid; ch < 512; ch += 256) {
        int r = ch >> 2, c4 = (ch & 3) * 4;
        int nb = (len - c4) * 4;
        nb = nb < 0 ? 0 : (nb > 16 ? 16 : nb);
        cp16(pb + (r * 20 + c4) * 4, P + (size_t)(q0 + r) * stride + c4, nb);
    }
    for (int ch = tid; ch < 320; ch += 256) {
        int r = ch / 20, c4 = (ch % 20) * 4;
        int rv = (r < len) ? 16 : 0;
        int rr = (r < len) ? r : (len - 1);
        cp16(vb + (r * 88 + c4) * 4, V + (size_t)(off + rr) * CD + c0 + c4, rv);
    }
    CP_COMMIT();

    float acc[2][5][4] = {};
    for (int s = 0; s < NS; s++) {
        if (s + 1 < NS) {
            int k0 = (s + 1) * 16;
            int bo = ((s + 1) & 1);
            for (int ch = tid; ch < 512; ch += 256) {
                int r = ch >> 2, c4 = (ch & 3) * 4;
                int nb = (len - (k0 + c4)) * 4;
                nb = nb < 0 ? 0 : (nb > 16 ? 16 : nb);
                cp16(pb + (bo * 2560 + r * 20 + c4) * 4,
                     P + (size_t)(q0 + r) * stride + k0 + c4, nb);
            }
            for (int ch = tid; ch < 320; ch += 256) {
                int r = ch / 20, c4 = (ch % 20) * 4;
                int rv = (k0 + r < len) ? 16 : 0;
                int rr = (k0 + r < len) ? (k0 + r) : (len - 1);
                cp16(vb + (bo * 1408 + r * 88 + c4) * 4,
                     V + (size_t)(off + rr) * CD + c0 + c4, rv);
            }
        }
        CP_COMMIT(); CP_WAIT1();
        __syncthreads();
        const float* Pb = Ps[s & 1];
        const uint32_t* Vb = (const uint32_t*)Vs[s & 1];
        #pragma unroll
        for (int k8 = 0; k8 < 16; k8 += 8) {
            int ac = k8 + (lane & 3);
            int ar = wm * 32 + (lane >> 2);
            uint32_t a[2][4];
            #pragma unroll
            for (int i = 0; i < 2; i++) {
                a[i][0] = rtf(Pb[(ar + i * 16) * 20 + ac]);
                a[i][1] = rtf(Pb[(ar + i * 16 + 8) * 20 + ac]);
                a[i][2] = rtf(Pb[(ar + i * 16) * 20 + ac + 4]);
                a[i][3] = rtf(Pb[(ar + i * 16 + 8) * 20 + ac + 4]);
            }
            #pragma unroll
            for (int j = 0; j < 5; j++) {
                int bc = wn * 40 + j * 8 + (lane >> 2);
                uint32_t b[2] = { Vb[ac * 88 + bc], Vb[(ac + 4) * 88 + bc] };
                mma_tf32(acc[0][j], a[0], b);
                mma_tf32(acc[1][j], a[1], b);
            }
        }
        __syncthreads();
    }
    int mi = wm * 32 + (lane >> 2);
    int nc = c0 + wn * 40 + 2 * (lane & 3);
    #pragma unroll
    for (int i = 0; i < 2; i++) {
        int r0 = q0 + mi + i * 16;
        int r1 = r0 + 8;
        #pragma unroll
        for (int j = 0; j < 5; j++) {
            int c = nc + j * 8;
            if (r0 < cnt) {
                size_t o = (size_t)(off + r0) * CD + c;
                g_hs[o] += acc[i][j][0]; g_hs[o + 1] += acc[i][j][1];
            }
            if (r1 < cnt) {
                size_t o = (size_t)(off + r1) * CD + c;
                g_hs[o] += acc[i][j][2]; g_hs[o + 1] += acc[i][j][3];
            }
        }
    }
}

// ---------------------------------------------------------------------------
__global__ void meanv_kernel() {
    int col = threadIdx.x;
    const float* V = g_proj + 8ull * PSEQ * CD;
    int r0 = blockIdx.x * 64;
    float s = 0.f;
    #pragma unroll 4
    for (int r = 0; r < 64; r++) {
        int row = r0 + r;
        s += V[(size_t)row * CD + col] * g_rowmask[row];
    }
    atomicAdd(&g_meanVo[col], s * (1.0f / SEQ));
}

__global__ void fb_kernel() {
    int row = blockIdx.x;
    int g = d_rowg[row];
    if (g < 0 || d_cntOut[g] != 0) return;
    for (int c = threadIdx.x; c < CD; c += 256)
        g_hs[(size_t)row * CD + c] += g_meanVo[c];
}

// ---------------------------------------------------------------------------
__global__ __launch_bounds__(256) void final_kernel(const float* __restrict__ resid,
                                                    float* __restrict__ Y) {
    __shared__ float Xs[2][128 * 20];
    __shared__ float Bs[2][128 * 20];
    __shared__ int ip[128];
    const float* Wo = g_wr + 9ull * CD * CD;
    int n0 = blockIdx.x * 128, m0 = blockIdx.y * 128;
    int tid = threadIdx.x, lane = tid & 31, warp = tid >> 5;
    int wm = warp & 3, wn = warp >> 2;
    if (tid < 128) ip[tid] = g_iperm[m0 + tid];
    __syncthreads();
    uint32_t xb = smem_u32(Xs), bb = smem_u32(Bs);

    for (int ch = tid; ch < 512; ch += 256) {
        int r = ch >> 2, c4 = (ch & 3) * 4;
        cp16(xb + (r * 20 + c4) * 4, g_hs + (size_t)ip[r] * CD + c4, 16);
        cp16(bb + (r * 20 + c4) * 4, Wo + (size_t)(n0 + r) * CD + c4, 16);
    }
    CP_COMMIT();

    float acc[2][8][4] = {};
    for (int s = 0; s < 40; s++) {
        if (s + 1 < 40) {
            int k0 = (s + 1) * 16;
            int bo = ((s + 1) & 1) * 2560;
            for (int ch = tid; ch < 512; ch += 256) {
                int r = ch >> 2, c4 = (ch & 3) * 4;
                cp16(xb + (bo + r * 20 + c4) * 4, g_hs + (size_t)ip[r] * CD + k0 + c4, 16);
                cp16(bb + (bo + r * 20 + c4) * 4, Wo + (size_t)(n0 + r) * CD + k0 + c4, 16);
            }
        }
        CP_COMMIT(); CP_WAIT1();
        __syncthreads();
        const float* Xb = Xs[s & 1];
        const uint32_t* Bb = (const uint32_t*)Bs[s & 1];
        #pragma unroll
        for (int k8 = 0; k8 < 16; k8 += 8) {
            int ac = k8 + (lane & 3);
            int ar = wm * 32 + (lane >> 2);
            uint32_t a[2][4];
            #pragma unroll
            for (int i = 0; i < 2; i++) {
                a[i][0] = rtf(Xb[(ar + i * 16) * 20 + ac]);
                a[i][1] = rtf(Xb[(ar + i * 16 + 8) * 20 + ac]);
                a[i][2] = rtf(Xb[(ar + i * 16) * 20 + ac + 4]);
                a[i][3] = rtf(Xb[(ar + i * 16 + 8) * 20 + ac + 4]);
            }
            #pragma unroll
            for (int j = 0; j < 8; j++) {
                int bc = wn * 64 + j * 8 + (lane >> 2);
                uint32_t b[2] = { Bb[bc * 20 + ac], Bb[bc * 20 + ac + 4] };
                mma_tf32(acc[0][j], a[0], b);
                mma_tf32(acc[1][j], a[1], b);
            }
        }
        __syncthreads();
    }
    int mi = wm * 32 + (lane >> 2);
    int nc = n0 + wn * 64 + 2 * (lane & 3);
    #pragma unroll
    for (int i = 0; i < 2; i++) {
        #pragma unroll
        for (int j = 0; j < 8; j++) {
            int c = nc + j * 8;
            size_t o0 = (size_t)(m0 + mi + i * 16) * CD + c;
            size_t o1 = (size_t)(m0 + mi + i * 16 + 8) * CD + c;
            Y[o0]     = acc[i][j][0] + resid[o0];
            Y[o0 + 1] = acc[i][j][1] + resid[o0 + 1];
            Y[o1]     = acc[i][j][2] + resid[o1];
            Y[o1 + 1] = acc[i][j][3] + resid[o1 + 1];
        }
    }
}

// ---------------------------------------------------------------------------
extern "C" void kernel_launch(void* const* d_in, const int* in_sizes, int n_in,
                              void* d_out, int out_size) {
    const float* hidden = (const float*)d_in[0];
    const int*   mask   = (const int*)d_in[1];
    const int*   inp    = (const int*)d_in[2];
    W10 w10;
    for (int i = 0; i < 9; i++) w10.w[i] = (const float*)d_in[3 + i];
    w10.w[9] = (const float*)d_in[12];
    float* out = (float*)d_out;

    const float s80  = 1.0f / sqrtf(80.0f);
    const float s640 = 1.0f / sqrtf(640.0f);

    cudaFuncSetAttribute(fa_kernel, cudaFuncAttributeMaxDynamicSharedMemorySize, FA_SMEM_BYTES);

    labels_kernel<<<16, 256>>>(mask, inp);
    prep_kernel<<<1, 256>>>();
    zero_hs_kernel<<<2880, 256>>>();
    round_x_kernel<<<10240, 256>>>(hidden);
    round_w_kernel<<<dim3(1600, 10), 256>>>(w10);

    proj_kernel<<<dim3(5, 32, 9), 256>>>();
    meanv_kernel<<<72, 640>>>();

    // both d=80 branches in one launch; epilogue atomicAdd into zeroed g_hs
    fa_kernel<<<dim3(40, 8, 2), 256, FA_SMEM_BYTES>>>(s80);

    scores_kernel<<<dim3(40, 32), 256>>>(3, 4, 640, s640);   // entity
    softmax_kernel<<<PSEQ, 256>>>();
    av_kernel<<<dim3(40, 8), 256>>>(5);                      // entity: accumulates

    fb_kernel<<<PSEQ, 256>>>();
    final_kernel<<<dim3(5, 32), 256>>>(hidden, out);
}